// round 6
// baseline (speedup 1.0000x reference)
#include <cuda_runtime.h>

#define N_NODES 100000
#define N_EDGES 1200000
#define F_IN 128
#define F_HID 256
#define F_OUT 40

// Scratch (static device globals — allocation-free per harness rules)
__device__ __align__(16) float g_deg[N_NODES];
__device__ __align__(16) float g_dinv[N_NODES];
__device__ __align__(16) float g_ag1[(size_t)N_NODES * F_IN];   // A @ x
__device__ __align__(16) float g_h  [(size_t)N_NODES * F_HID];  // relu(ag1@W1+b1)
__device__ __align__(16) float g_h2 [(size_t)N_NODES * F_OUT];  // h @ W2

// ---------------- degree / norm ----------------

__global__ void k_deg_init() {
    int i = blockIdx.x * blockDim.x + threadIdx.x;
    if (i < N_NODES) g_deg[i] = 1.0f;  // self-loop
}

__global__ void k_deg_count(const int* __restrict__ ei) {
    int e = blockIdx.x * blockDim.x + threadIdx.x;
    if (e >= N_EDGES) return;
    unsigned c = (unsigned)ei[N_EDGES + e];
    if (c < N_NODES) atomicAdd(&g_deg[c], 1.0f);
}

__global__ void k_dinv() {
    int i = blockIdx.x * blockDim.x + threadIdx.x;
    if (i < N_NODES) g_dinv[i] = rsqrtf(g_deg[i]);
}

// ---------------- layer 1 propagation: ag1 = A @ x ----------------

// self-loop term: ag1[i] = x[i] * dinv[i]^2   (also fully initializes ag1)
__global__ void k_init_ag1(const float* __restrict__ x) {
    int idx = blockIdx.x * blockDim.x + threadIdx.x;  // N*32 float4 chunks
    if (idx >= N_NODES * 32) return;
    int i = idx >> 5;
    float s = g_dinv[i]; s *= s;
    float4 v = ((const float4*)x)[idx];
    ((float4*)g_ag1)[idx] = make_float4(v.x * s, v.y * s, v.z * s, v.w * s);
}

// one warp per edge: 32 lanes x float4 = 128 floats
__global__ void k_prop1(const int* __restrict__ ei, const float* __restrict__ x) {
    int gid = blockIdx.x * blockDim.x + threadIdx.x;
    int e = gid >> 5;
    if (e >= N_EDGES) return;
    int lane = gid & 31;
    unsigned r = (unsigned)ei[e];
    unsigned c = (unsigned)ei[N_EDGES + e];
    if (r >= N_NODES || c >= N_NODES) return;
    float nrm = g_dinv[r] * g_dinv[c];
    float4 v = ((const float4*)(x + (size_t)r * F_IN))[lane];
    float* dst = g_ag1 + (size_t)c * F_IN + lane * 4;
    atomicAdd(dst + 0, v.x * nrm);
    atomicAdd(dst + 1, v.y * nrm);
    atomicAdd(dst + 2, v.z * nrm);
    atomicAdd(dst + 3, v.w * nrm);
}

// ---------------- tiled SGEMM core (BM=64, BN=64, BK=64, 256 thr, 4x4 microtile) ----------------

template <int KTOT, int NTOT, bool BIAS, bool RELU>
__device__ __forceinline__ void gemm_core(const float* __restrict__ A,
                                          const float* __restrict__ B,
                                          const float* __restrict__ bias,
                                          float* __restrict__ C, int M) {
    constexpr int BM = 64, BN = 64, BK = 64;
    __shared__ float As[BM][BK];
    __shared__ float Bs[BK][BN];

    int t  = threadIdx.x;       // 256 threads
    int tx = t & 15;            // 16 cols of 4
    int ty = t >> 4;            // 16 rows of 4
    int m0 = blockIdx.x * BM;
    int n0 = blockIdx.y * BN;

    float acc[4][4] = {};

    for (int kk = 0; kk < KTOT; kk += BK) {
        // load A tile (BM x BK): 1024 float4, 4 per thread, coalesced
        #pragma unroll
        for (int i = 0; i < 4; i++) {
            int f  = t + i * 256;
            int m  = f >> 4;      // BK/4 = 16 float4 per row
            int k4 = f & 15;
            float4 v = make_float4(0.f, 0.f, 0.f, 0.f);
            if (m0 + m < M)
                v = *(const float4*)(A + (size_t)(m0 + m) * KTOT + kk + k4 * 4);
            *(float4*)&As[m][k4 * 4] = v;
        }
        // load B tile (BK x BN): pad with zeros past NTOT (for NTOT=40)
        #pragma unroll
        for (int i = 0; i < 4; i++) {
            int f  = t + i * 256;
            int k  = f >> 4;
            int n4 = f & 15;
            float4 v = make_float4(0.f, 0.f, 0.f, 0.f);
            if (n0 + n4 * 4 < NTOT)
                v = *(const float4*)(B + (size_t)(kk + k) * NTOT + n0 + n4 * 4);
            *(float4*)&Bs[k][n4 * 4] = v;
        }
        __syncthreads();

        #pragma unroll
        for (int k = 0; k < BK; k += 4) {
            float4 a[4], b[4];
            #pragma unroll
            for (int i = 0; i < 4; i++) a[i] = *(const float4*)&As[ty * 4 + i][k];
            #pragma unroll
            for (int j = 0; j < 4; j++) b[j] = *(const float4*)&Bs[k + j][tx * 4];
            #pragma unroll
            for (int i = 0; i < 4; i++) {
                const float* av = (const float*)&a[i];
                #pragma unroll
                for (int j = 0; j < 4; j++) {
                    acc[i][j] += av[0] * ((const float*)&b[0])[j];
                    acc[i][j] += av[1] * ((const float*)&b[1])[j];
                    acc[i][j] += av[2] * ((const float*)&b[2])[j];
                    acc[i][j] += av[3] * ((const float*)&b[3])[j];
                }
            }
        }
        __syncthreads();
    }

    #pragma unroll
    for (int i = 0; i < 4; i++) {
        int m = m0 + ty * 4 + i;
        if (m >= M) continue;
        #pragma unroll
        for (int j = 0; j < 4; j++) {
            int n = n0 + tx * 4 + j;
            if (n >= NTOT) continue;
            float v = acc[i][j];
            if (BIAS) v += bias[n];
            if (RELU) v = fmaxf(v, 0.f);
            C[(size_t)m * NTOT + n] = v;
        }
    }
}

__global__ void k_gemm1(const float* __restrict__ W1, const float* __restrict__ b1) {
    gemm_core<F_IN, F_HID, true, true>(g_ag1, W1, b1, g_h, N_NODES);
}

__global__ void k_gemm2(const float* __restrict__ W2) {
    gemm_core<F_HID, F_OUT, false, false>(g_h, W2, nullptr, g_h2, N_NODES);
}

// ---------------- layer 2 propagation: out = A @ h2 + b2 ----------------

__global__ void k_init_out(const float* __restrict__ b2, float* __restrict__ out) {
    int idx = blockIdx.x * blockDim.x + threadIdx.x;  // N*10 float4 chunks
    if (idx >= N_NODES * 10) return;
    int i = idx / 10;
    int c = idx % 10;
    float s = g_dinv[i]; s *= s;
    float4 h = ((const float4*)g_h2)[idx];
    float4 b = ((const float4*)b2)[c];
    ((float4*)out)[idx] = make_float4(b.x + h.x * s, b.y + h.y * s,
                                      b.z + h.z * s, b.w + h.w * s);
}

// thread per (edge, float4 chunk): E*10 threads
__global__ void k_prop2(const int* __restrict__ ei, float* __restrict__ out) {
    int idx = blockIdx.x * blockDim.x + threadIdx.x;
    if (idx >= N_EDGES * 10) return;
    int e = idx / 10;
    int c = idx % 10;
    unsigned r  = (unsigned)ei[e];
    unsigned cl = (unsigned)ei[N_EDGES + e];
    if (r >= N_NODES || cl >= N_NODES) return;
    float nrm = g_dinv[r] * g_dinv[cl];
    float4 v = ((const float4*)(g_h2 + (size_t)r * F_OUT))[c];
    float* dst = out + (size_t)cl * F_OUT + c * 4;
    atomicAdd(dst + 0, v.x * nrm);
    atomicAdd(dst + 1, v.y * nrm);
    atomicAdd(dst + 2, v.z * nrm);
    atomicAdd(dst + 3, v.w * nrm);
}

// ---------------- launch ----------------

extern "C" void kernel_launch(void* const* d_in, const int* in_sizes, int n_in,
                              void* d_out, int out_size) {
    const float* x  = (const float*)d_in[0];
    const int*   ei = (const int*)d_in[1];
    const float* W1 = (const float*)d_in[2];
    const float* b1 = (const float*)d_in[3];
    const float* W2 = (const float*)d_in[4];
    const float* b2 = (const float*)d_in[5];
    float*       out = (float*)d_out;

    k_deg_init <<<(N_NODES + 255) / 256, 256>>>();
    k_deg_count<<<(N_EDGES + 255) / 256, 256>>>(ei);
    k_dinv     <<<(N_NODES + 255) / 256, 256>>>();

    k_init_ag1 <<<(N_NODES * 32 + 255) / 256, 256>>>(x);
    k_prop1    <<<(N_EDGES * 32 + 255) / 256, 256>>>(ei, x);

    k_gemm1    <<<dim3((N_NODES + 63) / 64, F_HID / 64), 256>>>(W1, b1);
    k_gemm2    <<<dim3((N_NODES + 63) / 64, 1), 256>>>(W2);

    k_init_out <<<(N_NODES * 10 + 255) / 256, 256>>>(b2, out);
    k_prop2    <<<(N_EDGES * 10 + 255) / 256, 256>>>(ei, out);
}